// round 10
// baseline (speedup 1.0000x reference)
#include <cuda_runtime.h>
#include <cuda_bf16.h>
#include <cstdint>

#define T_STEPS 512
#define BATCH   64
#define IDIM    256
#define HDIM    512
#define NCTA1   128
#define NTHR    256
#define NCTAR   64
#define NTHR2   512
#define JCOL    4
#define GR      16
#define GSTR    68
#define HROWP   264            // bf16 per padded A row (528 B; mod 128 = 16)
#define USTR    520            // bf16 per padded U row (1040 B; mod 128 = 16)

typedef unsigned long long ull;

// ---- persistent device scratch ----
__device__ float g_xw[(size_t)T_STEPS * NCTA1 * GR * BATCH];     // [t][jg][row16][b]
__device__ __nv_bfloat16 g_ha[2][2][128 * HROWP];                // [buf][khalf][row128 x HROWP]
__device__ unsigned int g_flags[NCTAR * 32];                     // 128B-padded per-CTA flags

// ---------------- helpers ----------------
__device__ __forceinline__ ull fma2(ull a, ull b, ull c) {
    ull d;
    asm("fma.rn.f32x2 %0, %1, %2, %3;" : "=l"(d) : "l"(a), "l"(b), "l"(c));
    return d;
}
__device__ __forceinline__ float hsum2(ull a) {
    return __uint_as_float((unsigned)(a & 0xffffffffu)) +
           __uint_as_float((unsigned)(a >> 32));
}
__device__ __forceinline__ float sigmoidf_(float v) {
    return __fdividef(1.0f, 1.0f + __expf(-v));
}
__device__ __forceinline__ unsigned ld_acquire_gpu(const unsigned* p) {
    unsigned v;
    asm volatile("ld.acquire.gpu.u32 %0, [%1];" : "=r"(v) : "l"(p) : "memory");
    return v;
}
__device__ __forceinline__ void st_release_gpu(unsigned* p, unsigned v) {
    asm volatile("st.release.gpu.u32 [%0], %1;" :: "l"(p), "r"(v) : "memory");
}
__device__ __forceinline__ uint32_t smem_u32(const void* p) {
    uint32_t a;
    asm("{ .reg .u64 t; cvta.to.shared.u64 t, %1; cvt.u32.u64 %0, t; }" : "=r"(a) : "l"(p));
    return a;
}
__device__ __forceinline__ void bulkcp(uint32_t dst, const void* src, uint32_t bytes,
                                       uint32_t mbar) {
    asm volatile(
        "cp.async.bulk.shared::cluster.global.mbarrier::complete_tx::bytes [%0], [%1], %2, [%3];"
        :: "r"(dst), "l"(src), "r"(bytes), "r"(mbar) : "memory");
}
#define MBARRIER_INIT(mb, c) \
    asm volatile("mbarrier.init.shared.b64 [%0], %1;" :: "r"((uint32_t)(mb)), "r"((uint32_t)(c)) : "memory")
#define MBARRIER_EXPECT_TX(mb, tx) \
    asm volatile("mbarrier.arrive.expect_tx.shared.b64 _, [%0], %1;" \
        :: "r"((uint32_t)(mb)), "r"((uint32_t)(tx)) : "memory")
#define MBARRIER_WAIT_PARITY(mb, par) do {                                            \
    uint32_t _mb = (uint32_t)(mb); uint32_t _p = (uint32_t)(par); uint32_t _done;     \
    asm volatile("{\n\t.reg .pred p;\n\t"                                             \
        "mbarrier.try_wait.parity.acquire.cta.shared::cta.b64 p, [%1], %2;\n\t"       \
        "selp.b32 %0, 1, 0, p;\n\t}" : "=r"(_done) : "r"(_mb), "r"(_p) : "memory");   \
    if (!_done) {                                                                     \
        asm volatile("{\n\t.reg .pred P1;\n\t"                                        \
            "WL_%=:\n\t"                                                              \
            "mbarrier.try_wait.parity.acquire.cta.shared::cta.b64 P1, [%0], %1, 0x989680;\n\t" \
            "@P1 bra.uni WD_%=;\n\t"                                                  \
            "bra.uni WL_%=;\n\t"                                                      \
            "WD_%=:\n\t}" :: "r"(_mb), "r"(_p) : "memory");                           \
    }                                                                                 \
} while (0)

// 16-wide fma2 update (phase-1 only, R5-verified)
#define MACBLK(kkv)                                                        \
    {                                                                      \
        ulonglong2 w0v = *(const ulonglong2*)(w0 + (kkv));                 \
        ulonglong2 w1v = *(const ulonglong2*)(w1 + (kkv));                 \
        ulonglong2 av;                                                     \
        av = *(const ulonglong2*)(a0p + (kkv));                            \
        A0  = fma2(w0v.x, av.x, A0);  A1  = fma2(w0v.y, av.y, A1);         \
        A2  = fma2(w1v.x, av.x, A2);  A3  = fma2(w1v.y, av.y, A3);         \
        av = *(const ulonglong2*)(a1p + (kkv));                            \
        A4  = fma2(w0v.x, av.x, A4);  A5  = fma2(w0v.y, av.y, A5);         \
        A6  = fma2(w1v.x, av.x, A6);  A7  = fma2(w1v.y, av.y, A7);         \
        av = *(const ulonglong2*)(a2p + (kkv));                            \
        A8  = fma2(w0v.x, av.x, A8);  A9  = fma2(w0v.y, av.y, A9);         \
        A10 = fma2(w1v.x, av.x, A10); A11 = fma2(w1v.y, av.y, A11);        \
        av = *(const ulonglong2*)(a3p + (kkv));                            \
        A12 = fma2(w0v.x, av.x, A12); A13 = fma2(w0v.y, av.y, A13);        \
        A14 = fma2(w1v.x, av.x, A14); A15 = fma2(w1v.y, av.y, A15);        \
    }

// ============================================================================
// Phase 1 (unchanged, R8/R9-verified): xw[t] = x_t @ Wall^T + (bW + bU)
// ============================================================================
#define P1_TT   32
#define P1_WXS  260
#define P1_CKP  132
#define P1_OFF_WX   0
#define P1_OFF_ASH  (P1_OFF_WX + GR * P1_WXS)
#define P1_OFF_GSM  (P1_OFF_ASH + 2 * BATCH * P1_CKP)
#define P1_OFF_BS   (P1_OFF_GSM + 2 * GR * GSTR)
#define P1_FLOATS   (P1_OFF_BS + GR)

__global__ void __launch_bounds__(NTHR, 2)
lstm_xw_kernel(const float* __restrict__ x,
               const float* __restrict__ Wf, const float* __restrict__ bWf,
               const float* __restrict__ Wi, const float* __restrict__ bWi,
               const float* __restrict__ Wo, const float* __restrict__ bWo,
               const float* __restrict__ Wc, const float* __restrict__ bWc,
               const float* __restrict__ bUf, const float* __restrict__ bUi,
               const float* __restrict__ bUo, const float* __restrict__ bUc)
{
    extern __shared__ float sm[];
    float* Wx  = sm + P1_OFF_WX;
    float* ash = sm + P1_OFF_ASH;
    float* gsm = sm + P1_OFF_GSM;
    float* bsm = sm + P1_OFF_BS;

    const int tid = threadIdx.x;
    const int kh  = tid >> 7;
    const int tl  = tid & 127;
    const int cg  = tl & 7;
    const int bg  = tl >> 3;
    const int jg  = blockIdx.x;
    const int j0  = jg * JCOL;
    const int t0  = blockIdx.y * P1_TT;

    {
        const float* Wg[4]  = {Wf, Wi, Wo, Wc};
        const float* bWg[4] = {bWf, bWi, bWo, bWc};
        const float* bUg[4] = {bUf, bUi, bUo, bUc};
        for (int idx = tid; idx < GR * IDIM; idx += NTHR) {
            int row = idx >> 8, k = idx & (IDIM - 1);
            int gate = row >> 2, j = row & 3;
            Wx[row * P1_WXS + k] = Wg[gate][(j0 + j) * IDIM + k];
        }
        if (tid < GR) {
            int gate = tid >> 2, j = tid & 3;
            bsm[tid] = bWg[gate][j0 + j] + bUg[gate][j0 + j];
        }
    }
    __syncthreads();

    const float* w0b = Wx + cg * P1_WXS + kh * 64;
    const float* w1b = Wx + (cg + 8) * P1_WXS + kh * 64;

    for (int tt = 0; tt < P1_TT; ++tt) {
        const int t = t0 + tt;
        const float* xt = x + (size_t)t * BATCH * IDIM;

        #pragma unroll
        for (int r = 0; r < 8; ++r) {
            int idx = tid + r * NTHR;
            int b = idx >> 5, q = idx & 31;
            float4 v = __ldg(reinterpret_cast<const float4*>(xt + b * IDIM + q * 4));
            *reinterpret_cast<float4*>(ash + b * P1_CKP + q * 4) = v;
        }
        __syncthreads();

        ull A0=0,A1=0,A2=0,A3=0,A4=0,A5=0,A6=0,A7=0;
        ull A8=0,A9=0,A10=0,A11=0,A12=0,A13=0,A14=0,A15=0;

        #pragma unroll
        for (int r = 0; r < 8; ++r) {
            int idx = tid + r * NTHR;
            int b = idx >> 5, q = idx & 31;
            float4 v = __ldg(reinterpret_cast<const float4*>(xt + b * IDIM + 128 + q * 4));
            *reinterpret_cast<float4*>(ash + BATCH * P1_CKP + b * P1_CKP + q * 4) = v;
        }
        {
            const float* abase = ash + kh * 64;
            const float* a0p = abase + (bg +  0) * P1_CKP;
            const float* a1p = abase + (bg + 16) * P1_CKP;
            const float* a2p = abase + (bg + 32) * P1_CKP;
            const float* a3p = abase + (bg + 48) * P1_CKP;
            const float* w0 = w0b;
            const float* w1 = w1b;
            #pragma unroll
            for (int kk = 0; kk < 64; kk += 4) MACBLK(kk)
        }
        __syncthreads();
        {
            const float* abase = ash + BATCH * P1_CKP + kh * 64;
            const float* a0p = abase + (bg +  0) * P1_CKP;
            const float* a1p = abase + (bg + 16) * P1_CKP;
            const float* a2p = abase + (bg + 32) * P1_CKP;
            const float* a3p = abase + (bg + 48) * P1_CKP;
            const float* w0 = w0b + 128;
            const float* w1 = w1b + 128;
            #pragma unroll
            for (int kk = 0; kk < 64; kk += 4) MACBLK(kk)
        }
        {
            float* g0 = gsm + kh * GR * GSTR + cg * GSTR + bg;
            float* g1 = gsm + kh * GR * GSTR + (cg + 8) * GSTR + bg;
            g0[ 0] = hsum2(A0)  + hsum2(A1);
            g1[ 0] = hsum2(A2)  + hsum2(A3);
            g0[16] = hsum2(A4)  + hsum2(A5);
            g1[16] = hsum2(A6)  + hsum2(A7);
            g0[32] = hsum2(A8)  + hsum2(A9);
            g1[32] = hsum2(A10) + hsum2(A11);
            g0[48] = hsum2(A12) + hsum2(A13);
            g1[48] = hsum2(A14) + hsum2(A15);
        }
        __syncthreads();
        {
            int row = tid >> 4;
            int b4  = (tid & 15) * 4;
            float4 p0 = *reinterpret_cast<float4*>(gsm + row * GSTR + b4);
            float4 p1 = *reinterpret_cast<float4*>(gsm + GR * GSTR + row * GSTR + b4);
            float bb = bsm[row];
            float4 o;
            o.x = p0.x + p1.x + bb;
            o.y = p0.y + p1.y + bb;
            o.z = p0.z + p1.z + bb;
            o.w = p0.w + p1.w + bb;
            *reinterpret_cast<float4*>(g_xw + (((size_t)t * NCTA1 + jg) * GR + row) * BATCH + b4) = o;
        }
        __syncthreads();
    }
}

// ============================================================================
// Phase 2: 64 CTAs x 8 h-cols, mma.sync bf16 hi/lo, flag-array barrier.
// ============================================================================
#define ACHUNK_BYTES (128 * HROWP * 2)        // 67584
#define XW_BYTES     (2 * GR * BATCH * 4)     // 8192 (two phase-1 jg blocks)

#define RB_MB0   0
#define RB_MB1   8
#define RB_MBX   16
#define RB_EB    24
#define RB_XW    64                            // 8192
#define RB_GSM   (RB_XW + XW_BYTES)            // 8256; 128*33*4 = 16896
#define RB_U     (RB_GSM + 16896)              // 25152; 2 * 32*USTR*2 = 66560
#define RB_A     (RB_U + 66560)                // 91712; 2 * 67584 = 135168
#define RB_TOTAL (RB_A + 2 * ACHUNK_BYTES)     // 226880

__global__ void __launch_bounds__(NTHR2, 1)
lstm_recur_kernel(const float* __restrict__ Uf, const float* __restrict__ Ui,
                  const float* __restrict__ Uo, const float* __restrict__ Uc,
                  float* __restrict__ out)
{
    extern __shared__ char smem[];
    const uint32_t smu = smem_u32(smem);
    float* xwf = (float*)(smem + RB_XW);
    float* gsm = (float*)(smem + RB_GSM);

    const int tid  = threadIdx.x;
    const int wid  = tid >> 5;
    const int lane = tid & 31;
    const int bx   = blockIdx.x;
    const int j0   = bx * 8;
    const int mt   = wid & 7;          // m-tile 0..7 (rows mt*16..+16)
    const int ng   = wid >> 3;         // n-group 0..1 -> n-tiles {2ng, 2ng+1}

    if (tid == 0) {
        MBARRIER_INIT(smu + RB_MB0, 1);
        MBARRIER_INIT(smu + RB_MB1, 1);
        MBARRIER_INIT(smu + RB_MBX, 1);
        *(unsigned*)(smem + RB_EB) = ld_acquire_gpu(&g_flags[bx * 32]);
    }
    // U -> split bf16 padded SMEM: 32 rows (gate*8 + jj), hi @ RB_U, lo @ +32*USTR*2
    {
        const float* Ug[4] = {Uf, Ui, Uo, Uc};
        for (int i = 0; i < 32; ++i) {
            int idx = tid + i * NTHR2;       // 0..16383
            int row = idx >> 9;              // 0..31
            int k   = idx & 511;
            float f = Ug[row >> 3][(j0 + (row & 7)) * HDIM + k];
            __nv_bfloat16 hi = __float2bfloat16_rn(f);
            __nv_bfloat16 lo = __float2bfloat16_rn(f - __bfloat162float(hi));
            *(__nv_bfloat16*)(smem + RB_U + (row * USTR + k) * 2) = hi;
            *(__nv_bfloat16*)(smem + RB_U + 32 * USTR * 2 + (row * USTR + k) * 2) = lo;
        }
        // xw(0): 2 jg blocks, contiguous 8192 B
        const float* src = g_xw + (size_t)(2 * bx) * GR * BATCH;
        float4 v = __ldg(reinterpret_cast<const float4*>(src + tid * 4));
        *reinterpret_cast<float4*>(xwf + tid * 4) = v;
    }
    __syncthreads();
    const unsigned base = *(unsigned*)(smem + RB_EB);

    float* hseq = out;
    float* hfin = out + (size_t)T_STEPS * BATCH * HDIM;
    float* cfin = hfin + BATCH * HDIM;

    // ldmatrix lane offsets (R9-verified formulas)
    const uint32_t a_lane = (uint32_t)(lane & 15) * (HROWP * 2) + (uint32_t)((lane >> 4) << 4);
    const uint32_t b_lane = (uint32_t)(lane & 7) * (USTR * 2) + (uint32_t)(((lane >> 3) & 1) << 4);
    const uint32_t abase0 = smu + RB_A + (uint32_t)mt * 16 * (HROWP * 2) + a_lane;
    const uint32_t bhi0   = smu + RB_U + (uint32_t)(2 * ng) * 8 * (USTR * 2) + b_lane;
    const uint32_t bhi1   = bhi0 + 8 * (USTR * 2);
    const uint32_t blo0   = bhi0 + 32 * USTR * 2;
    const uint32_t blo1   = bhi1 + 32 * USTR * 2;

    // elementwise identity: one (b, jj) per thread
    const int jj = tid & 7;
    const int eb = tid >> 3;
    float creg = 0.0f;
    const int hchunk = bx >> 5;
    const int hcol   = (j0 & 255) + jj;

    for (int t = 0; t < T_STEPS; ++t) {
        if (t > 0) {
            if (tid == 0) {
                MBARRIER_EXPECT_TX(smu + RB_MB0, ACHUNK_BYTES);
                bulkcp(smu + RB_A, &g_ha[t & 1][0][0], ACHUNK_BYTES, smu + RB_MB0);
                MBARRIER_EXPECT_TX(smu + RB_MB1, ACHUNK_BYTES);
                bulkcp(smu + RB_A + ACHUNK_BYTES, &g_ha[t & 1][1][0], ACHUNK_BYTES,
                       smu + RB_MB1);
            }

            float d00=0.f,d01=0.f,d02=0.f,d03=0.f;   // n-tile 2ng
            float d10=0.f,d11=0.f,d12=0.f,d13=0.f;   // n-tile 2ng+1

            #pragma unroll
            for (int c = 0; c < 2; ++c) {
                if (c == 0) { MBARRIER_WAIT_PARITY(smu + RB_MB0, (t - 1) & 1); }
                else        { MBARRIER_WAIT_PARITY(smu + RB_MB1, (t - 1) & 1); }
                const uint32_t ab = abase0 + (uint32_t)c * ACHUNK_BYTES;
                const uint32_t bofs = (uint32_t)c * 512;
                #pragma unroll
                for (int k = 0; k < 16; ++k) {
                    uint32_t a0, a1, a2, a3, b0, b1;
                    asm volatile(
                        "ldmatrix.sync.aligned.m8n8.x4.shared.b16 {%0,%1,%2,%3}, [%4];"
                        : "=r"(a0), "=r"(a1), "=r"(a2), "=r"(a3)
                        : "r"(ab + (uint32_t)k * 32));
                    // n-tile 0 of this group: hi then lo
                    asm volatile(
                        "ldmatrix.sync.aligned.m8n8.x2.shared.b16 {%0,%1}, [%2];"
                        : "=r"(b0), "=r"(b1) : "r"(bhi0 + bofs + (uint32_t)k * 32));
                    asm volatile(
                        "mma.sync.aligned.m16n8k16.row.col.f32.bf16.bf16.f32 "
                        "{%0,%1,%2,%3}, {%4,%5,%6,%7}, {%8,%9}, {%0,%1,%2,%3};"
                        : "+f"(d00), "+f"(d01), "+f"(d02), "+f"(d03)
                        : "r"(a0), "r"(a1), "r"(a2), "r"(a3), "r"(b0), "r"(b1));
                    asm volatile(
                        "ldmatrix.sync.aligned.m8n8.x2.shared.b16 {%0,%1}, [%2];"
                        : "=r"(b0), "=r"(b1) : "r"(blo0 + bofs + (uint32_t)k * 32));
                    asm volatile(
                        "mma.sync.aligned.m16n8k16.row.col.f32.bf16.bf16.f32 "
                        "{%0,%1,%2,%3}, {%4,%5,%6,%7}, {%8,%9}, {%0,%1,%2,%3};"
                        : "+f"(d00), "+f"(d01), "+f"(d02), "+f"(d03)
                        : "r"(a0), "r"(a1), "r"(a2), "r"(a3), "r"(b0), "r"(b1));
                    // n-tile 1 of this group
                    asm volatile(
                        "ldmatrix.sync.aligned.m8n8.x2.shared.b16 {%0,%1}, [%2];"
                        : "=r"(b0), "=r"(b1) : "r"(bhi1 + bofs + (uint32_t)k * 32));
                    asm volatile(
                        "mma.sync.aligned.m16n8k16.row.col.f32.bf16.bf16.f32 "
                        "{%0,%1,%2,%3}, {%4,%5,%6,%7}, {%8,%9}, {%0,%1,%2,%3};"
                        : "+f"(d10), "+f"(d11), "+f"(d12), "+f"(d13)
                        : "r"(a0), "r"(a1), "r"(a2), "r"(a3), "r"(b0), "r"(b1));
                    asm volatile(
                        "ldmatrix.sync.aligned.m8n8.x2.shared.b16 {%0,%1}, [%2];"
                        : "=r"(b0), "=r"(b1) : "r"(blo1 + bofs + (uint32_t)k * 32));
                    asm volatile(
                        "mma.sync.aligned.m16n8k16.row.col.f32.bf16.bf16.f32 "
                        "{%0,%1,%2,%3}, {%4,%5,%6,%7}, {%8,%9}, {%0,%1,%2,%3};"
                        : "+f"(d10), "+f"(d11), "+f"(d12), "+f"(d13)
                        : "r"(a0), "r"(a1), "r"(a2), "r"(a3), "r"(b0), "r"(b1));
                }
            }
            {
                int m = mt * 16 + (lane >> 2);
                int n0 = (2 * ng) * 8 + 2 * (lane & 3);
                int n1 = n0 + 8;
                gsm[m * 33 + n0]           = d00;
                gsm[m * 33 + n0 + 1]       = d01;
                gsm[(m + 8) * 33 + n0]     = d02;
                gsm[(m + 8) * 33 + n0 + 1] = d03;
                gsm[m * 33 + n1]           = d10;
                gsm[m * 33 + n1 + 1]       = d11;
                gsm[(m + 8) * 33 + n1]     = d12;
                gsm[(m + 8) * 33 + n1 + 1] = d13;
            }
        }
        __syncthreads();

        // elementwise LSTM update: all 512 threads, one (eb, jj) each
        {
            if (t > 0) MBARRIER_WAIT_PARITY(smu + RB_MBX, (t - 1) & 1);
            const int jgl = jj >> 2;           // which phase-1 block
            const int jin = jj & 3;
            float gv[4];
            #pragma unroll
            for (int g = 0; g < 4; ++g) {
                float v = xwf[jgl * (GR * BATCH) + (g * 4 + jin) * BATCH + eb];
                if (t > 0) {
                    int n = g * 8 + jj;
                    v += gsm[eb * 33 + n] + gsm[(eb + 64) * 33 + n];
                }
                gv[g] = v;
            }
            float fg = sigmoidf_(gv[0]);
            float ig = sigmoidf_(gv[1]);
            float og = sigmoidf_(gv[2]);
            float cc = tanhf(gv[3]);
            float cnew = fg * creg + ig * cc;
            creg = cnew;
            float h = og * tanhf(cnew);
            __nv_bfloat16 hi = __float2bfloat16_rn(h);
            __nv_bfloat16 lo = __float2bfloat16_rn(h - __bfloat162float(hi));
            int nb = (t + 1) & 1;
            g_ha[nb][hchunk][eb * HROWP + hcol]        = hi;
            g_ha[nb][hchunk][(eb + 64) * HROWP + hcol] = lo;
            __stcs(hseq + ((size_t)t * BATCH + eb) * HDIM + j0 + jj, h);
            if (t == T_STEPS - 1) {
                hfin[eb * HDIM + j0 + jj] = h;
                cfin[eb * HDIM + j0 + jj] = cnew;
            }
        }

        if (t < T_STEPS - 1) {
            __syncthreads();                   // all xwf reads done; h stores issued
            if (tid == 0) {
                // prefetch next xw into the (single) buffer
                MBARRIER_EXPECT_TX(smu + RB_MBX, XW_BYTES);
                bulkcp(smu + RB_XW,
                       g_xw + ((size_t)(t + 1) * NCTA1 + 2 * bx) * GR * BATCH,
                       XW_BYTES, smu + RB_MBX);
                // publish: release our flag (orders the h stores above)
                st_release_gpu(&g_flags[bx * 32], base + (unsigned)(t + 1));
            }
            // spin: thread i (i<64) acquires CTA i's flag
            if (tid < NCTAR) {
                unsigned target = base + (unsigned)(t + 1);
                while ((int)(ld_acquire_gpu(&g_flags[tid * 32]) - target) < 0) { }
            }
            __syncthreads();
        }
    }
}

extern "C" void kernel_launch(void* const* d_in, const int* in_sizes, int n_in,
                              void* d_out, int out_size)
{
    (void)in_sizes; (void)n_in; (void)out_size;
    const float* x   = (const float*)d_in[0];
    const float* Wf  = (const float*)d_in[1];
    const float* bWf = (const float*)d_in[2];
    const float* Wi  = (const float*)d_in[3];
    const float* bWi = (const float*)d_in[4];
    const float* Wo  = (const float*)d_in[5];
    const float* bWo = (const float*)d_in[6];
    const float* Wc  = (const float*)d_in[7];
    const float* bWc = (const float*)d_in[8];
    const float* Uf  = (const float*)d_in[9];
    const float* bUf = (const float*)d_in[10];
    const float* Ui  = (const float*)d_in[11];
    const float* bUi = (const float*)d_in[12];
    const float* Uo  = (const float*)d_in[13];
    const float* bUo = (const float*)d_in[14];
    const float* Uc  = (const float*)d_in[15];
    const float* bUc = (const float*)d_in[16];

    size_t p1_smem = P1_FLOATS * sizeof(float);
    cudaFuncSetAttribute(lstm_xw_kernel,
                         cudaFuncAttributeMaxDynamicSharedMemorySize, (int)p1_smem);
    cudaFuncSetAttribute(lstm_recur_kernel,
                         cudaFuncAttributeMaxDynamicSharedMemorySize, RB_TOTAL);

    dim3 g1(NCTA1, T_STEPS / P1_TT);
    lstm_xw_kernel<<<g1, NTHR, p1_smem>>>(
        x, Wf, bWf, Wi, bWi, Wo, bWo, Wc, bWc, bUf, bUi, bUo, bUc);

    lstm_recur_kernel<<<NCTAR, NTHR2, RB_TOTAL>>>(Uf, Ui, Uo, Uc, (float*)d_out);
}

// round 11
// speedup vs baseline: 1.1871x; 1.1871x over previous
#include <cuda_runtime.h>
#include <cuda_bf16.h>
#include <cstdint>

#define T_STEPS 512
#define BATCH   64
#define IDIM    256
#define HDIM    512
#define NCTA    128
#define NTHR    256
#define NTHR2   512
#define JCOL    4
#define GR      16
#define GSTR    68
#define HROWP   264            // bf16 per padded A row (528 B; 528 mod 128 = 16)
#define USTR    520            // bf16 per padded U row (1040 B; mod 128 = 16)

typedef unsigned long long ull;

// ---- persistent device scratch ----
__device__ float g_xw[(size_t)T_STEPS * NCTA * GR * BATCH];     // [t][jg][row16][b]
__device__ __nv_bfloat16 g_ha[2][2][128 * HROWP];               // [buf][khalf][row128 x HROWP]
__device__ unsigned int g_flags[NCTA * 32];                     // 128B-padded per-CTA flags

// ---------------- helpers ----------------
__device__ __forceinline__ ull fma2(ull a, ull b, ull c) {
    ull d;
    asm("fma.rn.f32x2 %0, %1, %2, %3;" : "=l"(d) : "l"(a), "l"(b), "l"(c));
    return d;
}
__device__ __forceinline__ float hsum2(ull a) {
    return __uint_as_float((unsigned)(a & 0xffffffffu)) +
           __uint_as_float((unsigned)(a >> 32));
}
__device__ __forceinline__ float sigmoidf_(float v) {
    return __fdividef(1.0f, 1.0f + __expf(-v));
}
__device__ __forceinline__ unsigned ld_acquire_gpu(const unsigned* p) {
    unsigned v;
    asm volatile("ld.acquire.gpu.u32 %0, [%1];" : "=r"(v) : "l"(p) : "memory");
    return v;
}
__device__ __forceinline__ void st_release_gpu(unsigned* p, unsigned v) {
    asm volatile("st.release.gpu.u32 [%0], %1;" :: "l"(p), "r"(v) : "memory");
}
__device__ __forceinline__ uint32_t smem_u32(const void* p) {
    uint32_t a;
    asm("{ .reg .u64 t; cvta.to.shared.u64 t, %1; cvt.u32.u64 %0, t; }" : "=r"(a) : "l"(p));
    return a;
}
__device__ __forceinline__ void bulkcp(uint32_t dst, const void* src, uint32_t bytes,
                                       uint32_t mbar) {
    asm volatile(
        "cp.async.bulk.shared::cluster.global.mbarrier::complete_tx::bytes [%0], [%1], %2, [%3];"
        :: "r"(dst), "l"(src), "r"(bytes), "r"(mbar) : "memory");
}
#define MBARRIER_INIT(mb, c) \
    asm volatile("mbarrier.init.shared.b64 [%0], %1;" :: "r"((uint32_t)(mb)), "r"((uint32_t)(c)) : "memory")
#define MBARRIER_EXPECT_TX(mb, tx) \
    asm volatile("mbarrier.arrive.expect_tx.shared.b64 _, [%0], %1;" \
        :: "r"((uint32_t)(mb)), "r"((uint32_t)(tx)) : "memory")
#define MBARRIER_WAIT_PARITY(mb, par) do {                                            \
    uint32_t _mb = (uint32_t)(mb); uint32_t _p = (uint32_t)(par); uint32_t _done;     \
    asm volatile("{\n\t.reg .pred p;\n\t"                                             \
        "mbarrier.try_wait.parity.acquire.cta.shared::cta.b64 p, [%1], %2;\n\t"       \
        "selp.b32 %0, 1, 0, p;\n\t}" : "=r"(_done) : "r"(_mb), "r"(_p) : "memory");   \
    if (!_done) {                                                                     \
        asm volatile("{\n\t.reg .pred P1;\n\t"                                        \
            "WL_%=:\n\t"                                                              \
            "mbarrier.try_wait.parity.acquire.cta.shared::cta.b64 P1, [%0], %1, 0x989680;\n\t" \
            "@P1 bra.uni WD_%=;\n\t"                                                  \
            "bra.uni WL_%=;\n\t"                                                      \
            "WD_%=:\n\t}" :: "r"(_mb), "r"(_p) : "memory");                           \
    }                                                                                 \
} while (0)

// 16-wide fma2 update (phase-1 only, R5-verified)
#define MACBLK(kkv)                                                        \
    {                                                                      \
        ulonglong2 w0v = *(const ulonglong2*)(w0 + (kkv));                 \
        ulonglong2 w1v = *(const ulonglong2*)(w1 + (kkv));                 \
        ulonglong2 av;                                                     \
        av = *(const ulonglong2*)(a0p + (kkv));                            \
        A0  = fma2(w0v.x, av.x, A0);  A1  = fma2(w0v.y, av.y, A1);         \
        A2  = fma2(w1v.x, av.x, A2);  A3  = fma2(w1v.y, av.y, A3);         \
        av = *(const ulonglong2*)(a1p + (kkv));                            \
        A4  = fma2(w0v.x, av.x, A4);  A5  = fma2(w0v.y, av.y, A5);         \
        A6  = fma2(w1v.x, av.x, A6);  A7  = fma2(w1v.y, av.y, A7);         \
        av = *(const ulonglong2*)(a2p + (kkv));                            \
        A8  = fma2(w0v.x, av.x, A8);  A9  = fma2(w0v.y, av.y, A9);         \
        A10 = fma2(w1v.x, av.x, A10); A11 = fma2(w1v.y, av.y, A11);        \
        av = *(const ulonglong2*)(a3p + (kkv));                            \
        A12 = fma2(w0v.x, av.x, A12); A13 = fma2(w0v.y, av.y, A13);        \
        A14 = fma2(w1v.x, av.x, A14); A15 = fma2(w1v.y, av.y, A15);        \
    }

// ============================================================================
// Phase 1 (unchanged, R8/R9-verified): xw[t] = x_t @ Wall^T + (bW + bU)
// ============================================================================
#define P1_TT   32
#define P1_WXS  260
#define P1_CKP  132
#define P1_OFF_WX   0
#define P1_OFF_ASH  (P1_OFF_WX + GR * P1_WXS)
#define P1_OFF_GSM  (P1_OFF_ASH + 2 * BATCH * P1_CKP)
#define P1_OFF_BS   (P1_OFF_GSM + 2 * GR * GSTR)
#define P1_FLOATS   (P1_OFF_BS + GR)

__global__ void __launch_bounds__(NTHR, 2)
lstm_xw_kernel(const float* __restrict__ x,
               const float* __restrict__ Wf, const float* __restrict__ bWf,
               const float* __restrict__ Wi, const float* __restrict__ bWi,
               const float* __restrict__ Wo, const float* __restrict__ bWo,
               const float* __restrict__ Wc, const float* __restrict__ bWc,
               const float* __restrict__ bUf, const float* __restrict__ bUi,
               const float* __restrict__ bUo, const float* __restrict__ bUc)
{
    extern __shared__ float sm[];
    float* Wx  = sm + P1_OFF_WX;
    float* ash = sm + P1_OFF_ASH;
    float* gsm = sm + P1_OFF_GSM;
    float* bsm = sm + P1_OFF_BS;

    const int tid = threadIdx.x;
    const int kh  = tid >> 7;
    const int tl  = tid & 127;
    const int cg  = tl & 7;
    const int bg  = tl >> 3;
    const int jg  = blockIdx.x;
    const int j0  = jg * JCOL;
    const int t0  = blockIdx.y * P1_TT;

    {
        const float* Wg[4]  = {Wf, Wi, Wo, Wc};
        const float* bWg[4] = {bWf, bWi, bWo, bWc};
        const float* bUg[4] = {bUf, bUi, bUo, bUc};
        for (int idx = tid; idx < GR * IDIM; idx += NTHR) {
            int row = idx >> 8, k = idx & (IDIM - 1);
            int gate = row >> 2, j = row & 3;
            Wx[row * P1_WXS + k] = Wg[gate][(j0 + j) * IDIM + k];
        }
        if (tid < GR) {
            int gate = tid >> 2, j = tid & 3;
            bsm[tid] = bWg[gate][j0 + j] + bUg[gate][j0 + j];
        }
    }
    __syncthreads();

    const float* w0b = Wx + cg * P1_WXS + kh * 64;
    const float* w1b = Wx + (cg + 8) * P1_WXS + kh * 64;

    for (int tt = 0; tt < P1_TT; ++tt) {
        const int t = t0 + tt;
        const float* xt = x + (size_t)t * BATCH * IDIM;

        #pragma unroll
        for (int r = 0; r < 8; ++r) {
            int idx = tid + r * NTHR;
            int b = idx >> 5, q = idx & 31;
            float4 v = __ldg(reinterpret_cast<const float4*>(xt + b * IDIM + q * 4));
            *reinterpret_cast<float4*>(ash + b * P1_CKP + q * 4) = v;
        }
        __syncthreads();

        ull A0=0,A1=0,A2=0,A3=0,A4=0,A5=0,A6=0,A7=0;
        ull A8=0,A9=0,A10=0,A11=0,A12=0,A13=0,A14=0,A15=0;

        #pragma unroll
        for (int r = 0; r < 8; ++r) {
            int idx = tid + r * NTHR;
            int b = idx >> 5, q = idx & 31;
            float4 v = __ldg(reinterpret_cast<const float4*>(xt + b * IDIM + 128 + q * 4));
            *reinterpret_cast<float4*>(ash + BATCH * P1_CKP + b * P1_CKP + q * 4) = v;
        }
        {
            const float* abase = ash + kh * 64;
            const float* a0p = abase + (bg +  0) * P1_CKP;
            const float* a1p = abase + (bg + 16) * P1_CKP;
            const float* a2p = abase + (bg + 32) * P1_CKP;
            const float* a3p = abase + (bg + 48) * P1_CKP;
            const float* w0 = w0b;
            const float* w1 = w1b;
            #pragma unroll
            for (int kk = 0; kk < 64; kk += 4) MACBLK(kk)
        }
        __syncthreads();
        {
            const float* abase = ash + BATCH * P1_CKP + kh * 64;
            const float* a0p = abase + (bg +  0) * P1_CKP;
            const float* a1p = abase + (bg + 16) * P1_CKP;
            const float* a2p = abase + (bg + 32) * P1_CKP;
            const float* a3p = abase + (bg + 48) * P1_CKP;
            const float* w0 = w0b + 128;
            const float* w1 = w1b + 128;
            #pragma unroll
            for (int kk = 0; kk < 64; kk += 4) MACBLK(kk)
        }
        {
            float* g0 = gsm + kh * GR * GSTR + cg * GSTR + bg;
            float* g1 = gsm + kh * GR * GSTR + (cg + 8) * GSTR + bg;
            g0[ 0] = hsum2(A0)  + hsum2(A1);
            g1[ 0] = hsum2(A2)  + hsum2(A3);
            g0[16] = hsum2(A4)  + hsum2(A5);
            g1[16] = hsum2(A6)  + hsum2(A7);
            g0[32] = hsum2(A8)  + hsum2(A9);
            g1[32] = hsum2(A10) + hsum2(A11);
            g0[48] = hsum2(A12) + hsum2(A13);
            g1[48] = hsum2(A14) + hsum2(A15);
        }
        __syncthreads();
        {
            int row = tid >> 4;
            int b4  = (tid & 15) * 4;
            float4 p0 = *reinterpret_cast<float4*>(gsm + row * GSTR + b4);
            float4 p1 = *reinterpret_cast<float4*>(gsm + GR * GSTR + row * GSTR + b4);
            float bb = bsm[row];
            float4 o;
            o.x = p0.x + p1.x + bb;
            o.y = p0.y + p1.y + bb;
            o.z = p0.z + p1.z + bb;
            o.w = p0.w + p1.w + bb;
            *reinterpret_cast<float4*>(g_xw + (((size_t)t * NCTA + jg) * GR + row) * BATCH + b4) = o;
        }
        __syncthreads();
    }
}

// ============================================================================
// Phase 2 (R9 topology, flag-array barrier): 128 CTAs x 4 h-cols, mma.sync.
// ============================================================================
#define ACHUNK_BYTES (128 * HROWP * 2)        // 67584
#define XW_BYTES     (GR * BATCH * 4)         // 4096

#define RB_MB0   0
#define RB_MB1   8
#define RB_MBX   16
#define RB_EB    24
#define RB_XW    64
#define RB_GSM   (RB_XW + 2 * XW_BYTES)       // 8256; gsm 128*20*4 = 10240
#define RB_U     (RB_GSM + 10240)             // hi 16*1040 + lo 16*1040 = 33280
#define RB_A     (RB_U + 33280)               // 2 * 67584 = 135168
#define RB_TOTAL (RB_A + 2 * ACHUNK_BYTES)    // 186944

__global__ void __launch_bounds__(NTHR2, 1)
lstm_recur_kernel(const float* __restrict__ Uf, const float* __restrict__ Ui,
                  const float* __restrict__ Uo, const float* __restrict__ Uc,
                  float* __restrict__ out)
{
    extern __shared__ char smem[];
    const uint32_t smu = smem_u32(smem);
    float* xwf = (float*)(smem + RB_XW);
    float* gsm = (float*)(smem + RB_GSM);

    const int tid  = threadIdx.x;
    const int wid  = tid >> 5;
    const int lane = tid & 31;
    const int bx   = blockIdx.x;
    const int j0   = bx * JCOL;
    const int mt   = wid & 7;          // m-tile 0..7 (rows mt*16..+16)
    const int nt   = wid >> 3;         // n-tile 0..1 (cols nt*8..+8)

    if (tid == 0) {
        MBARRIER_INIT(smu + RB_MB0, 1);
        MBARRIER_INIT(smu + RB_MB1, 1);
        MBARRIER_INIT(smu + RB_MBX, 1);
        *(unsigned*)(smem + RB_EB) = ld_acquire_gpu(&g_flags[bx * 32]);
    }
    // U -> split bf16 padded SMEM (hi @ RB_U, lo @ RB_U + 16*USTR*2)
    {
        const float* Ug[4] = {Uf, Ui, Uo, Uc};
        for (int i = 0; i < 16; ++i) {
            int idx = tid + i * NTHR2;       // 0..8191
            int row = idx >> 9;              // 0..15 (gate*4 + j)
            int k   = idx & 511;
            float f = Ug[row >> 2][(j0 + (row & 3)) * HDIM + k];
            __nv_bfloat16 hi = __float2bfloat16_rn(f);
            __nv_bfloat16 lo = __float2bfloat16_rn(f - __bfloat162float(hi));
            *(__nv_bfloat16*)(smem + RB_U + (row * USTR + k) * 2) = hi;
            *(__nv_bfloat16*)(smem + RB_U + 16 * USTR * 2 + (row * USTR + k) * 2) = lo;
        }
        if (tid < 256) {
            const float* src = g_xw + (size_t)bx * GR * BATCH;
            float4 v = __ldg(reinterpret_cast<const float4*>(src + tid * 4));
            *reinterpret_cast<float4*>(xwf + tid * 4) = v;
        }
    }
    __syncthreads();
    const unsigned base = *(unsigned*)(smem + RB_EB);

    float* hseq = out;
    float* hfin = out + (size_t)T_STEPS * BATCH * HDIM;
    float* cfin = hfin + BATCH * HDIM;

    // fragment lane address offsets (R9-verified)
    const uint32_t a_lane = (uint32_t)(lane & 15) * (HROWP * 2) + (uint32_t)((lane >> 4) << 4);
    const uint32_t b_lane = (uint32_t)(lane & 7) * (USTR * 2) + (uint32_t)(((lane >> 3) & 1) << 4);
    const uint32_t abase0 = smu + RB_A + (uint32_t)mt * 16 * (HROWP * 2) + a_lane;
    const uint32_t bhib   = smu + RB_U + (uint32_t)nt * 8 * (USTR * 2) + b_lane;
    const uint32_t blob   = bhib + 16 * USTR * 2;

    // elementwise identity
    const int jj = tid & 3;
    const int eb = tid >> 2;
    float creg = 0.0f;
    const int hchunk = j0 >> 8;
    const int hcc    = (j0 & 255);

    for (int t = 0; t < T_STEPS; ++t) {
        if (t > 0) {
            if (tid == 0) {
                MBARRIER_EXPECT_TX(smu + RB_MB0, ACHUNK_BYTES);
                bulkcp(smu + RB_A, &g_ha[t & 1][0][0], ACHUNK_BYTES, smu + RB_MB0);
                MBARRIER_EXPECT_TX(smu + RB_MB1, ACHUNK_BYTES);
                bulkcp(smu + RB_A + ACHUNK_BYTES, &g_ha[t & 1][1][0], ACHUNK_BYTES,
                       smu + RB_MB1);
            }

            float d0 = 0.f, d1 = 0.f, d2 = 0.f, d3 = 0.f;

            #pragma unroll
            for (int c = 0; c < 2; ++c) {
                if (c == 0) { MBARRIER_WAIT_PARITY(smu + RB_MB0, (t - 1) & 1); }
                else        { MBARRIER_WAIT_PARITY(smu + RB_MB1, (t - 1) & 1); }
                const uint32_t ab = abase0 + (uint32_t)c * ACHUNK_BYTES;
                const uint32_t bofs = (uint32_t)c * 512;   // k-byte offset within U row
                #pragma unroll
                for (int k = 0; k < 16; ++k) {
                    uint32_t a0, a1, a2, a3, b0, b1;
                    asm volatile(
                        "ldmatrix.sync.aligned.m8n8.x4.shared.b16 {%0,%1,%2,%3}, [%4];"
                        : "=r"(a0), "=r"(a1), "=r"(a2), "=r"(a3)
                        : "r"(ab + (uint32_t)k * 32));
                    asm volatile(
                        "ldmatrix.sync.aligned.m8n8.x2.shared.b16 {%0,%1}, [%2];"
                        : "=r"(b0), "=r"(b1) : "r"(bhib + bofs + (uint32_t)k * 32));
                    asm volatile(
                        "mma.sync.aligned.m16n8k16.row.col.f32.bf16.bf16.f32 "
                        "{%0,%1,%2,%3}, {%4,%5,%6,%7}, {%8,%9}, {%0,%1,%2,%3};"
                        : "+f"(d0), "+f"(d1), "+f"(d2), "+f"(d3)
                        : "r"(a0), "r"(a1), "r"(a2), "r"(a3), "r"(b0), "r"(b1));
                    asm volatile(
                        "ldmatrix.sync.aligned.m8n8.x2.shared.b16 {%0,%1}, [%2];"
                        : "=r"(b0), "=r"(b1) : "r"(blob + bofs + (uint32_t)k * 32));
                    asm volatile(
                        "mma.sync.aligned.m16n8k16.row.col.f32.bf16.bf16.f32 "
                        "{%0,%1,%2,%3}, {%4,%5,%6,%7}, {%8,%9}, {%0,%1,%2,%3};"
                        : "+f"(d0), "+f"(d1), "+f"(d2), "+f"(d3)
                        : "r"(a0), "r"(a1), "r"(a2), "r"(a3), "r"(b0), "r"(b1));
                }
            }
            {
                int m = mt * 16 + (lane >> 2);
                int n = nt * 8 + 2 * (lane & 3);
                gsm[m * 20 + n]           = d0;
                gsm[m * 20 + n + 1]       = d1;
                gsm[(m + 8) * 20 + n]     = d2;
                gsm[(m + 8) * 20 + n + 1] = d3;
            }
        }
        __syncthreads();

        // elementwise LSTM update (tid < 256)
        if (tid < 256) {
            if (t > 0) MBARRIER_WAIT_PARITY(smu + RB_MBX, (t - 1) & 1);
            const float* xwb = xwf + (t & 1) * (GR * BATCH);
            float gv[4];
            #pragma unroll
            for (int g = 0; g < 4; ++g) {
                float v = xwb[(g * JCOL + jj) * BATCH + eb];
                if (t > 0) {
                    int n = g * 4 + jj;
                    v += gsm[eb * 20 + n] + gsm[(eb + 64) * 20 + n];
                }
                gv[g] = v;
            }
            float fg = sigmoidf_(gv[0]);
            float ig = sigmoidf_(gv[1]);
            float og = sigmoidf_(gv[2]);
            float cc = tanhf(gv[3]);
            float cnew = fg * creg + ig * cc;
            creg = cnew;
            float h = og * tanhf(cnew);
            __nv_bfloat16 hi = __float2bfloat16_rn(h);
            __nv_bfloat16 lo = __float2bfloat16_rn(h - __bfloat162float(hi));
            int nb = (t + 1) & 1;
            g_ha[nb][hchunk][eb * HROWP + hcc + jj]        = hi;
            g_ha[nb][hchunk][(eb + 64) * HROWP + hcc + jj] = lo;
            __stcs(hseq + ((size_t)t * BATCH + eb) * HDIM + j0 + jj, h);
            if (t == T_STEPS - 1) {
                hfin[eb * HDIM + j0 + jj] = h;
                cfin[eb * HDIM + j0 + jj] = cnew;
            }
        }

        if (t < T_STEPS - 1) {
            if (tid == 0) {
                MBARRIER_EXPECT_TX(smu + RB_MBX, XW_BYTES);
                bulkcp(smu + RB_XW + ((t + 1) & 1) * XW_BYTES,
                       g_xw + ((size_t)(t + 1) * NCTA + bx) * GR * BATCH,
                       XW_BYTES, smu + RB_MBX);
            }
            // flag-array grid barrier: release own flag, acquire all in parallel
            __syncthreads();
            if (tid == 0)
                st_release_gpu(&g_flags[bx * 32], base + (unsigned)(t + 1));
            if (tid < NCTA) {
                unsigned target = base + (unsigned)(t + 1);
                while ((int)(ld_acquire_gpu(&g_flags[tid * 32]) - target) < 0) { }
            }
            __syncthreads();
        }
    }
}

extern "C" void kernel_launch(void* const* d_in, const int* in_sizes, int n_in,
                              void* d_out, int out_size)
{
    (void)in_sizes; (void)n_in; (void)out_size;
    const float* x   = (const float*)d_in[0];
    const float* Wf  = (const float*)d_in[1];
    const float* bWf = (const float*)d_in[2];
    const float* Wi  = (const float*)d_in[3];
    const float* bWi = (const float*)d_in[4];
    const float* Wo  = (const float*)d_in[5];
    const float* bWo = (const float*)d_in[6];
    const float* Wc  = (const float*)d_in[7];
    const float* bWc = (const float*)d_in[8];
    const float* Uf  = (const float*)d_in[9];
    const float* bUf = (const float*)d_in[10];
    const float* Ui  = (const float*)d_in[11];
    const float* bUi = (const float*)d_in[12];
    const float* Uo  = (const float*)d_in[13];
    const float* bUo = (const float*)d_in[14];
    const float* Uc  = (const float*)d_in[15];
    const float* bUc = (const float*)d_in[16];

    size_t p1_smem = P1_FLOATS * sizeof(float);
    cudaFuncSetAttribute(lstm_xw_kernel,
                         cudaFuncAttributeMaxDynamicSharedMemorySize, (int)p1_smem);
    cudaFuncSetAttribute(lstm_recur_kernel,
                         cudaFuncAttributeMaxDynamicSharedMemorySize, RB_TOTAL);

    dim3 g1(NCTA, T_STEPS / P1_TT);
    lstm_xw_kernel<<<g1, NTHR, p1_smem>>>(
        x, Wf, bWf, Wi, bWi, Wo, bWo, Wc, bWc, bUf, bUi, bUo, bUc);

    lstm_recur_kernel<<<NCTA, NTHR2, RB_TOTAL>>>(Uf, Ui, Uo, Uc, (float*)d_out);
}